// round 16
// baseline (speedup 1.0000x reference)
#include <cuda_runtime.h>
#include <cuda_fp16.h>
#include <cstdint>
#include <mma.h>

using namespace nvcuda;

// ---------------- problem constants ----------------
#define NA     50000
#define MPAD   50048            // 782 * 64
#define NEIGH  12
#define NEDGE  (NA * NEIGH)
#define MAXDEG 64
#define HID    128

// weight offsets inside g_wh (halves)
#define OW1B  0
#define OW1BR 61440
#define OW1A  122880
#define OW1AR 307200
#define OW2B  491520
#define OW2BR 507904
#define OW2A  524288
#define OW2AR 540672
#define WH_TOTAL 557056

// ---------------- scratch (static device globals; no allocation) ----------------
__device__ __half g_projB[(size_t)MPAD * 256];
__device__ __half g_projA[(size_t)MPAD * 256];
__device__ float  g_bo  [(size_t)MPAD * HID];
__device__ float  g_ao  [(size_t)MPAD * HID];
__device__ __half g_boH [(size_t)MPAD * HID];   // fp16 copies for next-layer GEMM A
__device__ __half g_aoH [(size_t)MPAD * HID];
__device__ int    g_cnt [NA];
__device__ int    g_inc [(size_t)NA * MAXDEG];
__device__ __half g_wh  [WH_TOTAL];

// ---------------- graph inversion ----------------
__global__ void zero_cnt_kernel() {
    int i = blockIdx.x * blockDim.x + threadIdx.x;
    if (i < NA) g_cnt[i] = 0;
}
__global__ void count_kernel(const int* __restrict__ nbr) {
    int e = blockIdx.x * blockDim.x + threadIdx.x;
    if (e >= NEDGE) return;
    int d = nbr[e];
    int p = atomicAdd(&g_cnt[d], 1);
    if (p < MAXDEG) g_inc[(size_t)d * MAXDEG + p] = e / NEIGH;
}

// ---------------- one-shot weight conversion fp32 -> fp16 ----------------
__global__ void wconv_kernel(const float* __restrict__ w1b,  const float* __restrict__ w1br,
                             const float* __restrict__ w1a,  const float* __restrict__ w1ar,
                             const float* __restrict__ w2b,  const float* __restrict__ w2br,
                             const float* __restrict__ w2a,  const float* __restrict__ w2ar) {
    int i = blockIdx.x * blockDim.x + threadIdx.x;
    const float* src; int off;
    if      (i < OW1BR)    { src = w1b;  off = OW1B;  }
    else if (i < OW1A)     { src = w1br; off = OW1BR; }
    else if (i < OW1AR)    { src = w1a;  off = OW1A;  }
    else if (i < OW2B)     { src = w1ar; off = OW1AR; }
    else if (i < OW2BR)    { src = w2b;  off = OW2B;  }
    else if (i < OW2A)     { src = w2br; off = OW2BR; }
    else if (i < OW2AR)    { src = w2a;  off = OW2A;  }
    else if (i < WH_TOTAL) { src = w2ar; off = OW2AR; }
    else return;
    g_wh[i] = __float2half_rn(src[i - off]);
}

// ---------------- exp2-form exp on FMA/ALU pipes (for x <= 0) ----------------
__device__ __forceinline__ float fast_exp(float x) {
    float t = x * 1.4426950408889634f;
    float n = rintf(t);
    float r = t - n;
    float p = fmaf(r, 1.33335581e-3f, 9.61812910e-3f);
    p = fmaf(p, r, 5.55041087e-2f);
    p = fmaf(p, r, 2.40226507e-1f);
    p = fmaf(p, r, 6.93147182e-1f);
    p = fmaf(p, r, 1.f);
    int e = __float2int_rn(n) + 127;
    float s = __int_as_float(max(e, 0) << 23);
    return p * s;
}

// ---------------- cp.async helpers ----------------
__device__ __forceinline__ uint32_t smem_u32(const void* p) {
    uint32_t a;
    asm("{ .reg .u64 t; cvta.to.shared.u64 t, %1; cvt.u32.u64 %0, t; }" : "=r"(a) : "l"(p));
    return a;
}
#define CP_ASYNC16(dst, src) \
    asm volatile("cp.async.cg.shared.global [%0], [%1], 16;" :: "r"(dst), "l"(src))
#define CP_COMMIT()  asm volatile("cp.async.commit_group;" ::: "memory")
#define CP_WAIT(n)   asm volatile("cp.async.wait_group %0;" :: "n"(n) : "memory")

// ---------------- fused fp16 wmma GEMM: proj[M64, 0..256] = A[M,K] @ [Wl;Wr]^T ----------------
// 256 threads, 8 warps = 2m x 4n, M=64 rows per CTA, 2 CTAs/SM.
// B and (MODE!=0) A cp.async'd as fp16 into 3-deep rings; MODE 0 A generated into 2-deep ring.
#define SMH_STRIDE 40
#define SMH_A_TILE (64 * SMH_STRIDE)        // halves (5120 B)
#define SMH_B_TILE (256 * SMH_STRIDE)       // halves (20480 B)
#define HA_BUF_BYTES (SMH_A_TILE * 2)
#define HB_BUF_BYTES (SMH_B_TILE * 2)
#define SM_TOTAL_GEN  (2 * SMH_A_TILE * 2 + 3 * SMH_B_TILE * 2)   // 71680 B
#define SM_TOTAL_LOAD (3 * SMH_A_TILE * 2 + 3 * SMH_B_TILE * 2)   // 76800 B

template<int MODE, int STEPS, int NPER>
__global__ void __launch_bounds__(256, 2)
hgemm_kernel(int wlOff, int wrOff,
             const float* __restrict__ fea, int K,
             float mu0, float dmu, float ig2, int psel)
{
    extern __shared__ char smc[];
    __half* const HAp = (__half*)smc;
    __half* const HBp = HAp + (MODE == 0 ? 2 : 3) * SMH_A_TILE;

    const __half* __restrict__ AH = (MODE == 1) ? g_boH : g_aoH;

    const int tid = threadIdx.x;
    const size_t rowbase = (size_t)blockIdx.x * 64;
    const int T = K >> 5;

    // ---- B loader: 1 thread per row (256 rows), 32 halves (64B) per chunk ----
    const int brow = tid;
    const __half* bSrc = g_wh + (brow < 128 ? wlOff + brow * K
                                            : wrOff + (brow - 128) * K);
    const uint32_t bDst0 = smem_u32(HBp) + brow * SMH_STRIDE * 2;

    // ---- A loader / generator: 4 threads per row (64 rows), 8 halves each ----
    const int arow = tid >> 2;
    const int ac8  = (tid & 3) << 3;
    const __half* aSrc = (MODE != 0)
        ? AH + (rowbase + arow) * (size_t)K + ac8 : (const __half*)0;
    const uint32_t aDst0 = smem_u32(HAp) + (arow * SMH_STRIDE + ac8) * 2;

    const int warp = tid >> 5;
    const int wm = warp >> 2;           // 0..1 : 32-row slice
    const int wn = warp & 3;            // 0..3 : 64-col slice

    const long grow = (long)rowbase + arow;
    const bool valid = grow < NA;
    const float* feaRow = (MODE == 0)
        ? fea + (size_t)(valid ? grow : 0) * NPER : (const float*)0;

    wmma::fragment<wmma::accumulator, 16, 16, 16, float> acc[2][4];
#pragma unroll
    for (int i = 0; i < 2; i++)
#pragma unroll
        for (int j = 0; j < 4; j++) wmma::fill_fragment(acc[i][j], 0.f);

    auto stage_async = [&](int tc) {
        const int k0 = tc << 5;                        // halves
        const uint32_t b3 = (uint32_t)(tc % 3);
        const uint32_t bd = bDst0 + b3 * HB_BUF_BYTES;
        CP_ASYNC16(bd,      bSrc + k0);
        CP_ASYNC16(bd + 16, bSrc + k0 + 8);
        CP_ASYNC16(bd + 32, bSrc + k0 + 16);
        CP_ASYNC16(bd + 48, bSrc + k0 + 24);
        if (MODE != 0)
            CP_ASYNC16(aDst0 + b3 * HA_BUF_BYTES, aSrc + k0);
        CP_COMMIT();
    };

    auto convert_chunk = [&](int tc) {                 // MODE 0 only: generate A
        if (MODE == 0) {
            __half* HA_ = HAp + (tc & 1) * SMH_A_TILE;
            const int kb = (tc << 5) + ac8;
            int p = kb / STEPS;
            int s = kb - p * STEPS;
            float mu = fmaf((float)s, dmu, mu0);
            float a  = feaRow[p];
            float vv[8];
#pragma unroll
            for (int j = 0; j < 8; j++) {
                float d = a - mu;
                vv[j] = fast_exp(-d * d * ig2);
                mu += dmu;
                if (++s == STEPS) {
                    s = 0; mu = mu0;
                    if (j < 7) { p++; a = feaRow[p]; }
                }
            }
            __half2 hh[4];
#pragma unroll
            for (int j = 0; j < 4; j++) {
                float v0 = valid ? vv[2 * j]     : 0.f;
                float v1 = valid ? vv[2 * j + 1] : 0.f;
                hh[j] = __floats2half2_rn(v0, v1);
            }
            *(uint4*)(HA_ + arow * SMH_STRIDE + ac8) = *(uint4*)&hh[0];
        }
    };

    auto mma_chunk = [&](int t) {
        __half* HA_ = HAp + (MODE == 0 ? (t & 1) : (t % 3)) * SMH_A_TILE;
        __half* HB_ = HBp + (t % 3) * SMH_B_TILE;
#pragma unroll
        for (int ks = 0; ks < 2; ks++) {
            wmma::fragment<wmma::matrix_a, 16, 16, 16, __half, wmma::row_major> af[2];
            wmma::fragment<wmma::matrix_b, 16, 16, 16, __half, wmma::col_major> bf[4];
#pragma unroll
            for (int mt = 0; mt < 2; mt++)
                wmma::load_matrix_sync(af[mt], HA_ + (wm * 32 + mt * 16) * SMH_STRIDE + ks * 16, SMH_STRIDE);
#pragma unroll
            for (int nt = 0; nt < 4; nt++)
                wmma::load_matrix_sync(bf[nt], HB_ + (wn * 64 + nt * 16) * SMH_STRIDE + ks * 16, SMH_STRIDE);
#pragma unroll
            for (int mt = 0; mt < 2; mt++)
#pragma unroll
                for (int nt = 0; nt < 4; nt++)
                    wmma::mma_sync(acc[mt][nt], af[mt], bf[nt], acc[mt][nt]);
        }
    };

    // ---- prologue ----
    stage_async(0);
    if (T > 1) { stage_async(1); CP_WAIT(1); }
    else       { CP_WAIT(0); }
    convert_chunk(0);

    // ---- mainloop: one barrier per chunk; 3-deep rings keep stage(t+2) vs mma(t) disjoint ----
    for (int t = 0; t < T; t++) {
        __syncthreads();
        mma_chunk(t);
        if (t + 2 < T) stage_async(t + 2);
        if (t + 1 < T) {
            if (t + 2 < T) { CP_WAIT(1); } else { CP_WAIT(0); }
            convert_chunk(t + 1);
        }
    }

    // ---- epilogue: direct fp16 fragment store ----
    __half* P = psel ? g_projA : g_projB;
    const int colbase = wn * 64;
#pragma unroll
    for (int mt = 0; mt < 2; mt++) {
        const size_t row = rowbase + wm * 32 + mt * 16;
#pragma unroll
        for (int nt = 0; nt < 4; nt++) {
            wmma::fragment<wmma::accumulator, 16, 16, 16, __half> hacc;
#pragma unroll
            for (int e = 0; e < hacc.num_elements; e++)
                hacc.x[e] = __float2half(acc[mt][nt].x[e]);
            wmma::store_matrix_sync(P + row * 256 + colbase + nt * 16,
                                    hacc, 256, wmma::mem_row_major);
        }
    }
}

// ---------------- mean-aggregate (gather) + bias + lin_r + ReLU; fp32 + fp16 outputs ----------------
__device__ __forceinline__ void gather_body(const __half* __restrict__ proj,
                                            const float* __restrict__ bias,
                                            float* __restrict__ out,
                                            __half* __restrict__ outH,
                                            int gw, int lane) {
    int deg = g_cnt[gw];
    int dcl = min(deg, MAXDEG);
    int src_l = (lane < dcl) ? g_inc[(size_t)gw * MAXDEG + lane] : 0;

    float4 acc = make_float4(0.f, 0.f, 0.f, 0.f);
    int p = 0;
    for (; p + 4 <= dcl && p + 4 <= 32; p += 4) {
        int s0 = __shfl_sync(0xffffffffu, src_l, p);
        int s1 = __shfl_sync(0xffffffffu, src_l, p + 1);
        int s2 = __shfl_sync(0xffffffffu, src_l, p + 2);
        int s3 = __shfl_sync(0xffffffffu, src_l, p + 3);
        uint2 h0 = *(const uint2*)(proj + (size_t)s0 * 256 + lane * 4);
        uint2 h1 = *(const uint2*)(proj + (size_t)s1 * 256 + lane * 4);
        uint2 h2 = *(const uint2*)(proj + (size_t)s2 * 256 + lane * 4);
        uint2 h3 = *(const uint2*)(proj + (size_t)s3 * 256 + lane * 4);
        float2 a0 = __half22float2(*(__half2*)&h0.x), b0 = __half22float2(*(__half2*)&h0.y);
        acc.x += a0.x; acc.y += a0.y; acc.z += b0.x; acc.w += b0.y;
        float2 a1 = __half22float2(*(__half2*)&h1.x), b1 = __half22float2(*(__half2*)&h1.y);
        acc.x += a1.x; acc.y += a1.y; acc.z += b1.x; acc.w += b1.y;
        float2 a2 = __half22float2(*(__half2*)&h2.x), b2 = __half22float2(*(__half2*)&h2.y);
        acc.x += a2.x; acc.y += a2.y; acc.z += b2.x; acc.w += b2.y;
        float2 a3 = __half22float2(*(__half2*)&h3.x), b3 = __half22float2(*(__half2*)&h3.y);
        acc.x += a3.x; acc.y += a3.y; acc.z += b3.x; acc.w += b3.y;
    }
    for (; p < dcl; p++) {
        int src = (p < 32) ? __shfl_sync(0xffffffffu, src_l, p)
                           : g_inc[(size_t)gw * MAXDEG + p];
        uint2 hv = *(const uint2*)(proj + (size_t)src * 256 + lane * 4);
        float2 f0 = __half22float2(*(__half2*)&hv.x);
        float2 f1 = __half22float2(*(__half2*)&hv.y);
        acc.x += f0.x; acc.y += f0.y; acc.z += f1.x; acc.w += f1.y;
    }
    float inv = 1.f / (float)max(deg, 1);
    uint2 pv = *(const uint2*)(proj + (size_t)gw * 256 + 128 + lane * 4);
    float2 p0 = __half22float2(*(__half2*)&pv.x);
    float2 p1 = __half22float2(*(__half2*)&pv.y);
    float4 bb = *(const float4*)(bias + lane * 4);
    float4 o;
    o.x = fmaxf(fmaf(acc.x, inv, bb.x + p0.x), 0.f);
    o.y = fmaxf(fmaf(acc.y, inv, bb.y + p0.y), 0.f);
    o.z = fmaxf(fmaf(acc.z, inv, bb.z + p1.x), 0.f);
    o.w = fmaxf(fmaf(acc.w, inv, bb.w + p1.y), 0.f);
    *(float4*)(out + (size_t)gw * HID + lane * 4) = o;
    __half2 hq[2];
    hq[0] = __floats2half2_rn(o.x, o.y);
    hq[1] = __floats2half2_rn(o.z, o.w);
    *(uint2*)(outH + (size_t)gw * HID + lane * 4) = *(uint2*)hq;
}

#define GATHER_BLOCKS ((NA * 32 + 255) / 256)   // 6250

__global__ void gather_kernel(const float* __restrict__ bias, int osel, int psel) {
    int gw   = (blockIdx.x * blockDim.x + threadIdx.x) >> 5;
    int lane = threadIdx.x & 31;
    if (gw >= NA) return;
    gather_body(psel ? g_projA : g_projB, bias,
                osel ? g_ao : g_bo, osel ? g_aoH : g_boH, gw, lane);
}

__global__ void gather2_kernel(const float* __restrict__ biasB, const float* __restrict__ biasA) {
    int half = (blockIdx.x >= GATHER_BLOCKS);
    int bx = blockIdx.x - (half ? GATHER_BLOCKS : 0);
    int gw   = (bx * blockDim.x + threadIdx.x) >> 5;
    int lane = threadIdx.x & 31;
    if (gw >= NA) return;
    if (half) gather_body(g_projA, biasA, g_ao, g_aoH, gw, lane);
    else      gather_body(g_projB, biasB, g_bo, g_boH, gw, lane);
}

// ---------------- crystal mean-pool + linear head ----------------
__global__ void pool_kernel(const int* __restrict__ crys,
                            const float* __restrict__ Wfc, const float* __restrict__ bfc,
                            float* __restrict__ out) {
    int b = blockIdx.x;
    int f = threadIdx.x;
    int start = crys[b * 2], end = crys[b * 2 + 1];
    const float* src = (f < 128) ? g_bo : g_ao;
    int fo = (f < 128) ? f : (f - 128);
    float s = 0.f;
    for (int a = start; a < end; a++) s += src[(size_t)a * HID + fo];
    __shared__ float pooled[256];
    pooled[f] = s / (float)(end - start);
    __syncthreads();
    int wid = f >> 5, lane = f & 31;
    if (wid < 2) {
        float d = 0.f;
        for (int i = lane; i < 256; i += 32) d += pooled[i] * Wfc[wid * 256 + i];
#pragma unroll
        for (int off = 16; off; off >>= 1) d += __shfl_down_sync(0xffffffffu, d, off);
        if (lane == 0) out[b * 2 + wid] = d + bfc[wid];
    }
}

// ---------------- host launcher ----------------
extern "C" void kernel_launch(void* const* d_in, const int* in_sizes, int n_in,
                              void* d_out, int out_size) {
    if (n_in < 19) return;

    int I_bond, I_angle, I_W1b, I_b1b, I_W1br, I_W1a, I_b1a, I_W1ar,
        I_W2b, I_b2b, I_W2br, I_W2a, I_b2a, I_W2ar, I_Wfc, I_bfc, I_nbr, I_crys;

    if (in_sizes[0] == 600000 && in_sizes[2] == 50000) {
        I_bond = 0; I_angle = 1; I_nbr = 3; I_crys = 4;
        I_W1b = 5;  I_b1b = 6;  I_W1br = 7;  I_W1a = 8;  I_b1a = 9;  I_W1ar = 10;
        I_W2b = 11; I_b2b = 12; I_W2br = 13; I_W2a = 14; I_b2a = 15; I_W2ar = 16;
        I_Wfc = 17; I_bfc = 18;
    } else if (in_sizes[0] == 600000) {
        I_bond = 0; I_angle = 1; I_W1b = 2; I_b1b = 3; I_W1br = 4;
        I_W1a = 5;  I_b1a = 6;  I_W1ar = 7; I_W2b = 8; I_b2b = 9; I_W2br = 10;
        I_W2a = 11; I_b2a = 12; I_W2ar = 13; I_Wfc = 14; I_bfc = 15;
        I_nbr = 17; I_crys = 18;
    } else {
        I_W1a = 0; I_W1ar = 1; I_W1b = 2; I_W1br = 3;
        I_W2a = 4; I_W2ar = 5; I_W2b = 6; I_W2br = 7; I_Wfc = 8;
        I_angle = 9; I_b1a = 10; I_b1b = 11; I_b2a = 12; I_b2b = 13; I_bfc = 14;
        I_bond = 15; I_crys = 16; I_nbr = 17;
    }

    const float* bond  = (const float*)d_in[I_bond];
    const float* angle = (const float*)d_in[I_angle];
    const int*   nbr   = (const int*)  d_in[I_nbr];
    const int*   crys  = (const int*)  d_in[I_crys];
    const float* b1b   = (const float*)d_in[I_b1b];
    const float* b1a   = (const float*)d_in[I_b1a];
    const float* b2b   = (const float*)d_in[I_b2b];
    const float* b2a   = (const float*)d_in[I_b2a];
    const float* Wfc   = (const float*)d_in[I_Wfc];
    const float* bfc   = (const float*)d_in[I_bfc];
    float* out = (float*)d_out;

    cudaFuncSetAttribute(hgemm_kernel<0, 40, 12>,  cudaFuncAttributeMaxDynamicSharedMemorySize, SM_TOTAL_GEN);
    cudaFuncSetAttribute(hgemm_kernel<0, 10, 144>, cudaFuncAttributeMaxDynamicSharedMemorySize, SM_TOTAL_GEN);
    cudaFuncSetAttribute(hgemm_kernel<1, 1, 1>,    cudaFuncAttributeMaxDynamicSharedMemorySize, SM_TOTAL_LOAD);
    cudaFuncSetAttribute(hgemm_kernel<2, 1, 1>,    cudaFuncAttributeMaxDynamicSharedMemorySize, SM_TOTAL_LOAD);

    const int gemmBlocks = MPAD / 64;   // 782

    zero_cnt_kernel<<<(NA + 255) / 256, 256>>>();                                     // 1
    count_kernel<<<(NEDGE + 255) / 256, 256>>>(nbr);                                  // 2
    wconv_kernel<<<(WH_TOTAL + 255) / 256, 256>>>(                                    // 3
        (const float*)d_in[I_W1b],  (const float*)d_in[I_W1br],
        (const float*)d_in[I_W1a],  (const float*)d_in[I_W1ar],
        (const float*)d_in[I_W2b],  (const float*)d_in[I_W2br],
        (const float*)d_in[I_W2a],  (const float*)d_in[I_W2ar]);
    hgemm_kernel<0, 40, 12><<<gemmBlocks, 256, SM_TOTAL_GEN>>>(                       // 4: bond L1 -> projB
        OW1B, OW1BR, bond, 480, 0.f, 8.f / 39.f, 25.f, 0);
    gather_kernel<<<GATHER_BLOCKS, 256>>>(b1b, 0, 0);                                 // 5: projB -> g_bo(+H)
    hgemm_kernel<1, 1, 1><<<gemmBlocks, 256, SM_TOTAL_LOAD>>>(                        // 6: bond L2 -> projB
        OW2B, OW2BR, (const float*)0, 128, 0.f, 0.f, 0.f, 0);
    hgemm_kernel<0, 10, 144><<<gemmBlocks, 256, SM_TOTAL_GEN>>>(                      // 7: angle L1 -> projA
        OW1A, OW1AR, angle, 1440, -1.f, 2.f / 9.f, 25.f, 1);
    gather2_kernel<<<2 * GATHER_BLOCKS, 256>>>(b2b, b1a);                             // 8
    hgemm_kernel<2, 1, 1><<<gemmBlocks, 256, SM_TOTAL_LOAD>>>(                        // 9: angle L2 -> projA
        OW2A, OW2AR, (const float*)0, 128, 0.f, 0.f, 0.f, 1);
    gather_kernel<<<GATHER_BLOCKS, 256>>>(b2a, 1, 1);                                 // 10
    pool_kernel<<<500, 256>>>(crys, Wfc, bfc, out);                                   // 11
}

// round 17
// speedup vs baseline: 1.3160x; 1.3160x over previous
#include <cuda_runtime.h>
#include <cuda_fp16.h>
#include <cstdint>
#include <mma.h>

using namespace nvcuda;

// ---------------- problem constants ----------------
#define NA     50000
#define MPAD   50048            // 391 * 128
#define NEIGH  12
#define NEDGE  (NA * NEIGH)
#define MAXDEG 64
#define HID    128

// weight offsets inside g_wh (halves)
#define OW1B  0
#define OW1BR 61440
#define OW1A  122880
#define OW1AR 307200
#define OW2B  491520
#define OW2BR 507904
#define OW2A  524288
#define OW2AR 540672
#define WH_TOTAL 557056

// ---------------- scratch (static device globals; no allocation) ----------------
__device__ __half g_projB[(size_t)MPAD * 256];
__device__ __half g_projA[(size_t)MPAD * 256];
__device__ float  g_bo  [(size_t)MPAD * HID];
__device__ float  g_ao  [(size_t)MPAD * HID];
__device__ __half g_boH [(size_t)MPAD * HID];   // fp16 copies for next-layer GEMM A
__device__ __half g_aoH [(size_t)MPAD * HID];
__device__ int    g_cnt [NA];
__device__ int    g_inc [(size_t)NA * MAXDEG];
__device__ __half g_wh  [WH_TOTAL];

// ---------------- graph inversion ----------------
__global__ void zero_cnt_kernel() {
    int i = blockIdx.x * blockDim.x + threadIdx.x;
    if (i < NA) g_cnt[i] = 0;
}
__global__ void count_kernel(const int* __restrict__ nbr) {
    int e = blockIdx.x * blockDim.x + threadIdx.x;
    if (e >= NEDGE) return;
    int d = nbr[e];
    int p = atomicAdd(&g_cnt[d], 1);
    if (p < MAXDEG) g_inc[(size_t)d * MAXDEG + p] = e / NEIGH;
}

// ---------------- one-shot weight conversion fp32 -> fp16 ----------------
__global__ void wconv_kernel(const float* __restrict__ w1b,  const float* __restrict__ w1br,
                             const float* __restrict__ w1a,  const float* __restrict__ w1ar,
                             const float* __restrict__ w2b,  const float* __restrict__ w2br,
                             const float* __restrict__ w2a,  const float* __restrict__ w2ar) {
    int i = blockIdx.x * blockDim.x + threadIdx.x;
    const float* src; int off;
    if      (i < OW1BR)    { src = w1b;  off = OW1B;  }
    else if (i < OW1A)     { src = w1br; off = OW1BR; }
    else if (i < OW1AR)    { src = w1a;  off = OW1A;  }
    else if (i < OW2B)     { src = w1ar; off = OW1AR; }
    else if (i < OW2BR)    { src = w2b;  off = OW2B;  }
    else if (i < OW2A)     { src = w2br; off = OW2BR; }
    else if (i < OW2AR)    { src = w2a;  off = OW2A;  }
    else if (i < WH_TOTAL) { src = w2ar; off = OW2AR; }
    else return;
    g_wh[i] = __float2half_rn(src[i - off]);
}

// ---------------- exp2-form exp on FMA/ALU pipes (for x <= 0) ----------------
__device__ __forceinline__ float fast_exp(float x) {
    float t = x * 1.4426950408889634f;
    float n = rintf(t);
    float r = t - n;
    float p = fmaf(r, 1.33335581e-3f, 9.61812910e-3f);
    p = fmaf(p, r, 5.55041087e-2f);
    p = fmaf(p, r, 2.40226507e-1f);
    p = fmaf(p, r, 6.93147182e-1f);
    p = fmaf(p, r, 1.f);
    int e = __float2int_rn(n) + 127;
    float s = __int_as_float(max(e, 0) << 23);
    return p * s;
}

// ---------------- cp.async helpers ----------------
__device__ __forceinline__ uint32_t smem_u32(const void* p) {
    uint32_t a;
    asm("{ .reg .u64 t; cvta.to.shared.u64 t, %1; cvt.u32.u64 %0, t; }" : "=r"(a) : "l"(p));
    return a;
}
#define CP_ASYNC16(dst, src) \
    asm volatile("cp.async.cg.shared.global [%0], [%1], 16;" :: "r"(dst), "l"(src))
#define CP_COMMIT()  asm volatile("cp.async.commit_group;" ::: "memory")
#define CP_WAIT(n)   asm volatile("cp.async.wait_group %0;" :: "n"(n) : "memory")

// ---------------- fused fp16 wmma GEMM device body ----------------
// 512 threads, 16 warps = 4m x 4n, M=128, N=256. fp16 B (and fp16 A in MODE 1/2)
// cp.async'd into 3-deep rings; MODE 0 A generated into 2-deep ring. 1 barrier/chunk.
#define SMH_STRIDE 40
#define SMH_A_TILE (128 * SMH_STRIDE)       // halves (10240 B)
#define SMH_B_TILE (256 * SMH_STRIDE)       // halves (20480 B)
#define HA_BUF_BYTES (SMH_A_TILE * 2)
#define HB_BUF_BYTES (SMH_B_TILE * 2)
#define SM_TOTAL_GEN  (2 * SMH_A_TILE * 2 + 3 * SMH_B_TILE * 2)   // 81920 B
#define SM_TOTAL_LOAD (3 * SMH_A_TILE * 2 + 3 * SMH_B_TILE * 2)   // 92160 B

template<int MODE, int STEPS, int NPER>
__device__ __forceinline__ void hgemm_dev(
    int wlOff, int wrOff, const float* __restrict__ fea, int K,
    float mu0, float dmu, float ig2, __half* __restrict__ P,
    char* smc, int bx)
{
    __half* const HAp = (__half*)smc;
    __half* const HBp = HAp + (MODE == 0 ? 2 : 3) * SMH_A_TILE;

    const __half* __restrict__ AH = (MODE == 1) ? g_boH : g_aoH;

    const int tid = threadIdx.x;
    const size_t rowbase = (size_t)bx * 128;
    const int T = K >> 5;

    // ---- B loader: 2 threads per row (256 rows), 16 halves (32B) each ----
    const int brow = tid >> 1;
    const int bhc  = (tid & 1) << 4;
    const __half* bSrc = g_wh + (brow < 128 ? wlOff + brow * K
                                            : wrOff + (brow - 128) * K) + bhc;
    const uint32_t bDst0 = smem_u32(HBp) + (brow * SMH_STRIDE + bhc) * 2;

    // ---- A loader / generator: 4 threads per row (128 rows), 8 halves each ----
    const int arow = tid >> 2;
    const int ac8  = (tid & 3) << 3;
    const __half* aSrc = (MODE != 0)
        ? AH + (rowbase + arow) * (size_t)K + ac8 : (const __half*)0;
    const uint32_t aDst0 = smem_u32(HAp) + (arow * SMH_STRIDE + ac8) * 2;

    const int warp = tid >> 5;
    const int wm = warp >> 2;           // 0..3 : 32-row slice
    const int wn = warp & 3;            // 0..3 : 64-col slice

    const long grow = (long)rowbase + arow;
    const bool valid = grow < NA;
    const float* feaRow = (MODE == 0)
        ? fea + (size_t)(valid ? grow : 0) * NPER : (const float*)0;

    wmma::fragment<wmma::accumulator, 16, 16, 16, float> acc[2][4];
#pragma unroll
    for (int i = 0; i < 2; i++)
#pragma unroll
        for (int j = 0; j < 4; j++) wmma::fill_fragment(acc[i][j], 0.f);

    auto stage_async = [&](int tc) {
        const int k0 = tc << 5;                        // halves
        const uint32_t b3 = (uint32_t)(tc % 3);
        const uint32_t bd = bDst0 + b3 * HB_BUF_BYTES;
        CP_ASYNC16(bd,      bSrc + k0);
        CP_ASYNC16(bd + 16, bSrc + k0 + 8);
        if (MODE != 0)
            CP_ASYNC16(aDst0 + b3 * HA_BUF_BYTES, aSrc + k0);
        CP_COMMIT();
    };

    auto convert_chunk = [&](int tc) {                 // MODE 0 only: generate A
        if (MODE == 0) {
            __half* HA_ = HAp + (tc & 1) * SMH_A_TILE;
            const int kb = (tc << 5) + ac8;
            int p = kb / STEPS;
            int s = kb - p * STEPS;
            float mu = fmaf((float)s, dmu, mu0);
            float a  = feaRow[p];
            float vv[8];
#pragma unroll
            for (int j = 0; j < 8; j++) {
                float d = a - mu;
                vv[j] = fast_exp(-d * d * ig2);
                mu += dmu;
                if (++s == STEPS) {
                    s = 0; mu = mu0;
                    if (j < 7) { p++; a = feaRow[p]; }
                }
            }
            __half2 hh[4];
#pragma unroll
            for (int j = 0; j < 4; j++) {
                float v0 = valid ? vv[2 * j]     : 0.f;
                float v1 = valid ? vv[2 * j + 1] : 0.f;
                hh[j] = __floats2half2_rn(v0, v1);
            }
            *(uint4*)(HA_ + arow * SMH_STRIDE + ac8) = *(uint4*)&hh[0];
        }
    };

    auto mma_chunk = [&](int t) {
        __half* HA_ = HAp + (MODE == 0 ? (t & 1) : (t % 3)) * SMH_A_TILE;
        __half* HB_ = HBp + (t % 3) * SMH_B_TILE;
#pragma unroll
        for (int ks = 0; ks < 2; ks++) {
            wmma::fragment<wmma::matrix_a, 16, 16, 16, __half, wmma::row_major> af[2];
            wmma::fragment<wmma::matrix_b, 16, 16, 16, __half, wmma::col_major> bf[4];
#pragma unroll
            for (int mt = 0; mt < 2; mt++)
                wmma::load_matrix_sync(af[mt], HA_ + (wm * 32 + mt * 16) * SMH_STRIDE + ks * 16, SMH_STRIDE);
#pragma unroll
            for (int nt = 0; nt < 4; nt++)
                wmma::load_matrix_sync(bf[nt], HB_ + (wn * 64 + nt * 16) * SMH_STRIDE + ks * 16, SMH_STRIDE);
#pragma unroll
            for (int mt = 0; mt < 2; mt++)
#pragma unroll
                for (int nt = 0; nt < 4; nt++)
                    wmma::mma_sync(acc[mt][nt], af[mt], bf[nt], acc[mt][nt]);
        }
    };

    // ---- prologue ----
    stage_async(0);
    if (T > 1) { stage_async(1); CP_WAIT(1); }
    else       { CP_WAIT(0); }
    convert_chunk(0);

    // ---- mainloop: one barrier per chunk; 3-deep rings keep stage(t+2) vs mma(t) disjoint ----
    for (int t = 0; t < T; t++) {
        __syncthreads();
        mma_chunk(t);
        if (t + 2 < T) stage_async(t + 2);
        if (t + 1 < T) {
            if (t + 2 < T) { CP_WAIT(1); } else { CP_WAIT(0); }
            convert_chunk(t + 1);
        }
    }

    // ---- epilogue: direct fp16 fragment store ----
    const int colbase = wn * 64;
#pragma unroll
    for (int mt = 0; mt < 2; mt++) {
        const size_t row = rowbase + wm * 32 + mt * 16;
#pragma unroll
        for (int nt = 0; nt < 4; nt++) {
            wmma::fragment<wmma::accumulator, 16, 16, 16, __half> hacc;
#pragma unroll
            for (int e = 0; e < hacc.num_elements; e++)
                hacc.x[e] = __float2half(acc[mt][nt].x[e]);
            wmma::store_matrix_sync(P + row * 256 + colbase + nt * 16,
                                    hacc, 256, wmma::mem_row_major);
        }
    }
}

#define GEMM_BLOCKS (MPAD / 128)   // 391

// ---- merged layer-1 GEMM: angle CTAs first (longer), bond CTAs fill the tail ----
__global__ void __launch_bounds__(512, 1)
l1_kernel(const float* __restrict__ bond, const float* __restrict__ angle) {
    extern __shared__ char smc[];
    if (blockIdx.x < GEMM_BLOCKS)
        hgemm_dev<0, 10, 144>(OW1A, OW1AR, angle, 1440, -1.f, 2.f / 9.f, 25.f,
                              g_projA, smc, blockIdx.x);
    else
        hgemm_dev<0, 40, 12>(OW1B, OW1BR, bond, 480, 0.f, 8.f / 39.f, 25.f,
                             g_projB, smc, blockIdx.x - GEMM_BLOCKS);
}

// ---- merged layer-2 GEMM ----
__global__ void __launch_bounds__(512, 1)
l2_kernel() {
    extern __shared__ char smc[];
    if (blockIdx.x < GEMM_BLOCKS)
        hgemm_dev<2, 1, 1>(OW2A, OW2AR, (const float*)0, 128, 0.f, 0.f, 0.f,
                           g_projA, smc, blockIdx.x);
    else
        hgemm_dev<1, 1, 1>(OW2B, OW2BR, (const float*)0, 128, 0.f, 0.f, 0.f,
                           g_projB, smc, blockIdx.x - GEMM_BLOCKS);
}

// ---------------- mean-aggregate (gather) + bias + lin_r + ReLU; fp32 + fp16 outputs ----------------
__device__ __forceinline__ void gather_body(const __half* __restrict__ proj,
                                            const float* __restrict__ bias,
                                            float* __restrict__ out,
                                            __half* __restrict__ outH,
                                            int gw, int lane) {
    int deg = g_cnt[gw];
    int dcl = min(deg, MAXDEG);
    int src_l = (lane < dcl) ? g_inc[(size_t)gw * MAXDEG + lane] : 0;

    float4 acc = make_float4(0.f, 0.f, 0.f, 0.f);
    int p = 0;
    for (; p + 4 <= dcl && p + 4 <= 32; p += 4) {
        int s0 = __shfl_sync(0xffffffffu, src_l, p);
        int s1 = __shfl_sync(0xffffffffu, src_l, p + 1);
        int s2 = __shfl_sync(0xffffffffu, src_l, p + 2);
        int s3 = __shfl_sync(0xffffffffu, src_l, p + 3);
        uint2 h0 = *(const uint2*)(proj + (size_t)s0 * 256 + lane * 4);
        uint2 h1 = *(const uint2*)(proj + (size_t)s1 * 256 + lane * 4);
        uint2 h2 = *(const uint2*)(proj + (size_t)s2 * 256 + lane * 4);
        uint2 h3 = *(const uint2*)(proj + (size_t)s3 * 256 + lane * 4);
        float2 a0 = __half22float2(*(__half2*)&h0.x), b0 = __half22float2(*(__half2*)&h0.y);
        acc.x += a0.x; acc.y += a0.y; acc.z += b0.x; acc.w += b0.y;
        float2 a1 = __half22float2(*(__half2*)&h1.x), b1 = __half22float2(*(__half2*)&h1.y);
        acc.x += a1.x; acc.y += a1.y; acc.z += b1.x; acc.w += b1.y;
        float2 a2 = __half22float2(*(__half2*)&h2.x), b2 = __half22float2(*(__half2*)&h2.y);
        acc.x += a2.x; acc.y += a2.y; acc.z += b2.x; acc.w += b2.y;
        float2 a3 = __half22float2(*(__half2*)&h3.x), b3 = __half22float2(*(__half2*)&h3.y);
        acc.x += a3.x; acc.y += a3.y; acc.z += b3.x; acc.w += b3.y;
    }
    for (; p < dcl; p++) {
        int src = (p < 32) ? __shfl_sync(0xffffffffu, src_l, p)
                           : g_inc[(size_t)gw * MAXDEG + p];
        uint2 hv = *(const uint2*)(proj + (size_t)src * 256 + lane * 4);
        float2 f0 = __half22float2(*(__half2*)&hv.x);
        float2 f1 = __half22float2(*(__half2*)&hv.y);
        acc.x += f0.x; acc.y += f0.y; acc.z += f1.x; acc.w += f1.y;
    }
    float inv = 1.f / (float)max(deg, 1);
    uint2 pv = *(const uint2*)(proj + (size_t)gw * 256 + 128 + lane * 4);
    float2 p0 = __half22float2(*(__half2*)&pv.x);
    float2 p1 = __half22float2(*(__half2*)&pv.y);
    float4 bb = *(const float4*)(bias + lane * 4);
    float4 o;
    o.x = fmaxf(fmaf(acc.x, inv, bb.x + p0.x), 0.f);
    o.y = fmaxf(fmaf(acc.y, inv, bb.y + p0.y), 0.f);
    o.z = fmaxf(fmaf(acc.z, inv, bb.z + p1.x), 0.f);
    o.w = fmaxf(fmaf(acc.w, inv, bb.w + p1.y), 0.f);
    *(float4*)(out + (size_t)gw * HID + lane * 4) = o;
    __half2 hq[2];
    hq[0] = __floats2half2_rn(o.x, o.y);
    hq[1] = __floats2half2_rn(o.z, o.w);
    *(uint2*)(outH + (size_t)gw * HID + lane * 4) = *(uint2*)hq;
}

#define GATHER_BLOCKS ((NA * 32 + 255) / 256)   // 6250

// dual gather: first half -> (biasB, projB -> g_bo); second half -> (biasA, projA -> g_ao)
__global__ void gather2_kernel(const float* __restrict__ biasB, const float* __restrict__ biasA) {
    int half = (blockIdx.x >= GATHER_BLOCKS);
    int bx = blockIdx.x - (half ? GATHER_BLOCKS : 0);
    int gw   = (bx * blockDim.x + threadIdx.x) >> 5;
    int lane = threadIdx.x & 31;
    if (gw >= NA) return;
    if (half) gather_body(g_projA, biasA, g_ao, g_aoH, gw, lane);
    else      gather_body(g_projB, biasB, g_bo, g_boH, gw, lane);
}

// ---------------- crystal mean-pool + linear head ----------------
__global__ void pool_kernel(const int* __restrict__ crys,
                            const float* __restrict__ Wfc, const float* __restrict__ bfc,
                            float* __restrict__ out) {
    int b = blockIdx.x;
    int f = threadIdx.x;
    int start = crys[b * 2], end = crys[b * 2 + 1];
    const float* src = (f < 128) ? g_bo : g_ao;
    int fo = (f < 128) ? f : (f - 128);
    float s = 0.f;
    for (int a = start; a < end; a++) s += src[(size_t)a * HID + fo];
    __shared__ float pooled[256];
    pooled[f] = s / (float)(end - start);
    __syncthreads();
    int wid = f >> 5, lane = f & 31;
    if (wid < 2) {
        float d = 0.f;
        for (int i = lane; i < 256; i += 32) d += pooled[i] * Wfc[wid * 256 + i];
#pragma unroll
        for (int off = 16; off; off >>= 1) d += __shfl_down_sync(0xffffffffu, d, off);
        if (lane == 0) out[b * 2 + wid] = d + bfc[wid];
    }
}

// ---------------- host launcher ----------------
extern "C" void kernel_launch(void* const* d_in, const int* in_sizes, int n_in,
                              void* d_out, int out_size) {
    if (n_in < 19) return;

    int I_bond, I_angle, I_W1b, I_b1b, I_W1br, I_W1a, I_b1a, I_W1ar,
        I_W2b, I_b2b, I_W2br, I_W2a, I_b2a, I_W2ar, I_Wfc, I_bfc, I_nbr, I_crys;

    if (in_sizes[0] == 600000 && in_sizes[2] == 50000) {
        I_bond = 0; I_angle = 1; I_nbr = 3; I_crys = 4;
        I_W1b = 5;  I_b1b = 6;  I_W1br = 7;  I_W1a = 8;  I_b1a = 9;  I_W1ar = 10;
        I_W2b = 11; I_b2b = 12; I_W2br = 13; I_W2a = 14; I_b2a = 15; I_W2ar = 16;
        I_Wfc = 17; I_bfc = 18;
    } else if (in_sizes[0] == 600000) {
        I_bond = 0; I_angle = 1; I_W1b = 2; I_b1b = 3; I_W1br = 4;
        I_W1a = 5;  I_b1a = 6;  I_W1ar = 7; I_W2b = 8; I_b2b = 9; I_W2br = 10;
        I_W2a = 11; I_b2a = 12; I_W2ar = 13; I_Wfc = 14; I_bfc = 15;
        I_nbr = 17; I_crys = 18;
    } else {
        I_W1a = 0; I_W1ar = 1; I_W1b = 2; I_W1br = 3;
        I_W2a = 4; I_W2ar = 5; I_W2b = 6; I_W2br = 7; I_Wfc = 8;
        I_angle = 9; I_b1a = 10; I_b1b = 11; I_b2a = 12; I_b2b = 13; I_bfc = 14;
        I_bond = 15; I_crys = 16; I_nbr = 17;
    }

    const float* bond  = (const float*)d_in[I_bond];
    const float* angle = (const float*)d_in[I_angle];
    const int*   nbr   = (const int*)  d_in[I_nbr];
    const int*   crys  = (const int*)  d_in[I_crys];
    const float* b1b   = (const float*)d_in[I_b1b];
    const float* b1a   = (const float*)d_in[I_b1a];
    const float* b2b   = (const float*)d_in[I_b2b];
    const float* b2a   = (const float*)d_in[I_b2a];
    const float* Wfc   = (const float*)d_in[I_Wfc];
    const float* bfc   = (const float*)d_in[I_bfc];
    float* out = (float*)d_out;

    cudaFuncSetAttribute(l1_kernel, cudaFuncAttributeMaxDynamicSharedMemorySize, SM_TOTAL_GEN);
    cudaFuncSetAttribute(l2_kernel, cudaFuncAttributeMaxDynamicSharedMemorySize, SM_TOTAL_LOAD);

    zero_cnt_kernel<<<(NA + 255) / 256, 256>>>();                                     // 1
    count_kernel<<<(NEDGE + 255) / 256, 256>>>(nbr);                                  // 2
    wconv_kernel<<<(WH_TOTAL + 255) / 256, 256>>>(                                    // 3
        (const float*)d_in[I_W1b],  (const float*)d_in[I_W1br],
        (const float*)d_in[I_W1a],  (const float*)d_in[I_W1ar],
        (const float*)d_in[I_W2b],  (const float*)d_in[I_W2br],
        (const float*)d_in[I_W2a],  (const float*)d_in[I_W2ar]);
    l1_kernel<<<2 * GEMM_BLOCKS, 512, SM_TOTAL_GEN>>>(bond, angle);                   // 4: L1 both paths
    gather2_kernel<<<2 * GATHER_BLOCKS, 256>>>(b1b, b1a);                             // 5: both L1 gathers
    l2_kernel<<<2 * GEMM_BLOCKS, 512, SM_TOTAL_LOAD>>>();                             // 6: L2 both paths
    gather2_kernel<<<2 * GATHER_BLOCKS, 256>>>(b2b, b2a);                             // 7: both L2 gathers
    pool_kernel<<<500, 256>>>(crys, Wfc, bfc, out);                                   // 8
}